// round 11
// baseline (speedup 1.0000x reference)
#include <cuda_runtime.h>
#include <cuda_fp16.h>
#include <mma.h>
#include <math.h>

using namespace nvcuda;

#define NMAX 100000
#define EMAX 1600000

// ---------------- device scratch ----------------
__device__ float  g_dinv[NMAX];
__device__ int    g_cnt[NMAX];
__device__ int    g_fill[NMAX];
__device__ int    g_rowptr[NMAX + 1];
__device__ int    g_bsum[256];
__device__ int    g_col[EMAX];
__device__ __half g_hA[(size_t)NMAX * 128];
__device__ __half g_hB[(size_t)NMAX * 128];
__device__ __half g_hH2[(size_t)NMAX * 128];
__device__ __half g_hD[(size_t)NMAX * 64];

// ---------------- CSR build ----------------
__global__ void zero_counts_kernel(int n) {
    int i = blockIdx.x * blockDim.x + threadIdx.x;
    if (i < n) { g_cnt[i] = 0; g_fill[i] = 0; }
}

__global__ void count_edges_kernel(const int* __restrict__ dst, int e) {
    int i = blockIdx.x * blockDim.x + threadIdx.x;
    if (i < e) atomicAdd(&g_cnt[dst[i]], 1);
}

__global__ void scan1_kernel(int n) {
    __shared__ int s[1024];
    int tid = threadIdx.x;
    int i = blockIdx.x * 1024 + tid;
    int v = (i < n) ? g_cnt[i] : 0;
    s[tid] = v;
    __syncthreads();
    for (int off = 1; off < 1024; off <<= 1) {
        int t2 = (tid >= off) ? s[tid - off] : 0;
        __syncthreads();
        s[tid] += t2;
        __syncthreads();
    }
    if (i < n) {
        g_rowptr[i] = s[tid] - v;
        g_dinv[i] = rsqrtf((float)(v + 1));
    }
    if (tid == 1023) g_bsum[blockIdx.x] = s[1023];
}

__global__ void scan2_kernel(int nb) {
    __shared__ int s[128];
    int tid = threadIdx.x;
    int v = (tid < nb) ? g_bsum[tid] : 0;
    s[tid] = v;
    __syncthreads();
    for (int off = 1; off < 128; off <<= 1) {
        int t2 = (tid >= off) ? s[tid - off] : 0;
        __syncthreads();
        s[tid] += t2;
        __syncthreads();
    }
    if (tid < nb) g_bsum[tid] = s[tid] - v;
    if (tid == 127) g_bsum[nb] = s[127];
}

__global__ void scan3_kernel(int n, int nb) {
    int i = blockIdx.x * blockDim.x + threadIdx.x;
    if (i < n) g_rowptr[i] += g_bsum[i >> 10];
    if (i == 0) g_rowptr[n] = g_bsum[nb];
}

__global__ void scatter_edges_kernel(const int* __restrict__ src,
                                     const int* __restrict__ dst, int e) {
    int i = blockIdx.x * blockDim.x + threadIdx.x;
    if (i < e) {
        int d = dst[i];
        int p = g_rowptr[d] + atomicAdd(&g_fill[d], 1);
        g_col[p] = src[i];
    }
}

// ---------------- wmma GEMM (vectorized loads) ----------------
#define GBM 128
#define GBN 64

template <int K, int C, int K1, int EPI, typename TA>
__global__ __launch_bounds__(128) void gemm_wmma_kernel(
    const TA* __restrict__ A1, const __half* __restrict__ A2,
    const float* __restrict__ W, const float* __restrict__ bias,
    void* __restrict__ outv, int n) {
    constexpr int LDW = GBN + 8;   // halves
    constexpr int LDA = K + 8;     // halves
    constexpr int LDS_ = GBN + 4;  // floats
    extern __shared__ char smraw[];
    __half* Ws = (__half*)smraw;
    __half* As = (__half*)(smraw + (size_t)K * LDW * 2);
    float*  St = (float*)(smraw + (size_t)K * LDW * 2);

    const int t = threadIdx.x;
    const int w = t >> 5;
    const int row0 = blockIdx.x * GBM;
    const int bn0 = blockIdx.y * GBN;

    // load W tile [K][BN]: float4 loads, packed half2 x2 store (8B)
    for (int idx = t; idx < K * GBN / 4; idx += 128) {
        int k = idx / (GBN / 4);
        int j = (idx % (GBN / 4)) * 4;
        float4 wv = *(const float4*)(W + (size_t)k * C + bn0 + j);
        uint2 pk;
        __half2* h = (__half2*)&pk;
        h[0] = __floats2half2_rn(wv.x, wv.y);
        h[1] = __floats2half2_rn(wv.z, wv.w);
        *(uint2*)&Ws[k * LDW + j] = pk;
    }

    // load A tile [BM][K], pre-scaled by dinv when EPI==0
    constexpr int CPR = K / 8;  // 8-half chunks per row
#pragma unroll
    for (int it = 0; it < GBM * CPR / 128; it++) {
        int cidx = t + it * 128;
        int r = cidx / CPR;
        int kq = (cidx % CPR) * 8;
        int gr = row0 + r;
        uint4 pk = make_uint4(0, 0, 0, 0);
        if (gr < n) {
            float s = (EPI == 0) ? g_dinv[gr] : 1.0f;
            __half2 s2 = __float2half2_rn(s);
            if (kq < K1) {
                if (sizeof(TA) == 2) {  // half source: uint4 load + half2 scale
                    uint4 raw = *(const uint4*)((const __half*)A1 +
                                                (size_t)gr * K1 + kq);
                    __half2* h = (__half2*)&raw;
                    if (EPI == 0) {
#pragma unroll
                        for (int q = 0; q < 4; q++) h[q] = __hmul2(h[q], s2);
                    }
                    pk = raw;
                } else {  // float source: two float4 loads
                    const float* p = (const float*)A1 + (size_t)gr * K1 + kq;
                    float4 a = *(const float4*)p;
                    float4 b = *(const float4*)(p + 4);
                    __half2* h = (__half2*)&pk;
                    h[0] = __floats2half2_rn(s * a.x, s * a.y);
                    h[1] = __floats2half2_rn(s * a.z, s * a.w);
                    h[2] = __floats2half2_rn(s * b.x, s * b.y);
                    h[3] = __floats2half2_rn(s * b.z, s * b.w);
                }
            } else {
                uint4 raw = *(const uint4*)(A2 + (size_t)gr * (K - K1) +
                                            (kq - K1));
                __half2* h = (__half2*)&raw;
                if (EPI == 0) {
#pragma unroll
                    for (int q = 0; q < 4; q++) h[q] = __hmul2(h[q], s2);
                }
                pk = raw;
            }
        }
        *(uint4*)&As[r * LDA + kq] = pk;
    }
    __syncthreads();

    wmma::fragment<wmma::accumulator, 16, 16, 16, float> acc[2][4];
#pragma unroll
    for (int i = 0; i < 2; i++)
#pragma unroll
        for (int j = 0; j < 4; j++) wmma::fill_fragment(acc[i][j], 0.f);

    for (int k = 0; k < K; k += 16) {
        wmma::fragment<wmma::matrix_a, 16, 16, 16, __half, wmma::row_major> af[2];
        wmma::fragment<wmma::matrix_b, 16, 16, 16, __half, wmma::row_major> bfr[4];
        wmma::load_matrix_sync(af[0], As + (w * 32 + 0) * LDA + k, LDA);
        wmma::load_matrix_sync(af[1], As + (w * 32 + 16) * LDA + k, LDA);
#pragma unroll
        for (int j = 0; j < 4; j++)
            wmma::load_matrix_sync(bfr[j], Ws + k * LDW + j * 16, LDW);
#pragma unroll
        for (int i = 0; i < 2; i++)
#pragma unroll
            for (int j = 0; j < 4; j++)
                wmma::mma_sync(acc[i][j], af[i], bfr[j], acc[i][j]);
    }

    __syncthreads();
#pragma unroll
    for (int i = 0; i < 2; i++)
#pragma unroll
        for (int j = 0; j < 4; j++)
            wmma::store_matrix_sync(St + (w * 32 + i * 16) * LDS_ + j * 16,
                                    acc[i][j], LDS_, wmma::mem_row_major);
    __syncthreads();

    const int lane = t & 7;
    const int rsub = t >> 3;
#pragma unroll
    for (int g = 0; g < 8; g++) {
        int r = g * 16 + rsub;
        int gr = row0 + r;
        if (gr >= n) continue;
        const float* sp = St + r * LDS_ + lane * 8;
        if (EPI == 0) {
            uint4 pk;
            __half2* h = (__half2*)&pk;
            h[0] = __floats2half2_rn(sp[0], sp[1]);
            h[1] = __floats2half2_rn(sp[2], sp[3]);
            h[2] = __floats2half2_rn(sp[4], sp[5]);
            h[3] = __floats2half2_rn(sp[6], sp[7]);
            *(uint4*)((__half*)outv + (size_t)gr * C + bn0 + lane * 8) = pk;
        } else {
            float* outp = (float*)outv + (size_t)gr * C + bn0 + lane * 8;
            const float* bp = bias + bn0 + lane * 8;
            float ov[8];
#pragma unroll
            for (int q = 0; q < 8; q++)
                ov[q] = 1.f / (1.f + __expf(-(sp[q] + bp[q])));
            *(float4*)outp = *(float4*)ov;
            *(float4*)(outp + 4) = *(float4*)(ov + 4);
        }
    }
}

// ---------------- aggregation: pipelined index prefetch ----------
template <int D, bool RELU>
__global__ __launch_bounds__(256) void agg_kernel(
    const __half* __restrict__ hs, const float* __restrict__ bias,
    __half* __restrict__ out, int n) {
    constexpr int LPN = D / 8;  // lanes per node, 8 halfs each
    int idx = blockIdx.x * blockDim.x + threadIdx.x;
    int v = idx / LPN;
    int lane = idx % LPN;
    if (v >= n) return;
    int c = lane * 8;
    const uint4* base = (const uint4*)hs;
    size_t selfidx = ((size_t)v * D + c) >> 3;

    float acc[8];
    {
        uint4 sv = base[selfidx];
        const __half2* h = (const __half2*)&sv;
#pragma unroll
        for (int q = 0; q < 4; q++) {
            float2 f = __half22float2(h[q]);
            acc[2 * q] = f.x; acc[2 * q + 1] = f.y;
        }
    }
    int e = g_rowptr[v];
    const int end = g_rowptr[v + 1];
    int rem = end - e;

    // software pipeline: prefetch next 4 indices while current gathers land
    int nu0 = 0, nu1 = 0, nu2 = 0, nu3 = 0;
    bool have = rem >= 4;
    if (have) {
        nu0 = g_col[e]; nu1 = g_col[e + 1];
        nu2 = g_col[e + 2]; nu3 = g_col[e + 3];
    }
    while (have) {
        int u0 = nu0, u1 = nu1, u2 = nu2, u3 = nu3;
        e += 4; rem -= 4;
        have = rem >= 4;
        if (have) {  // issue next index loads BEFORE consuming gathers
            nu0 = g_col[e]; nu1 = g_col[e + 1];
            nu2 = g_col[e + 2]; nu3 = g_col[e + 3];
        }
        uint4 m0 = base[((size_t)u0 * D + c) >> 3];
        uint4 m1 = base[((size_t)u1 * D + c) >> 3];
        uint4 m2 = base[((size_t)u2 * D + c) >> 3];
        uint4 m3 = base[((size_t)u3 * D + c) >> 3];
        const __half2* h0 = (const __half2*)&m0;
        const __half2* h1 = (const __half2*)&m1;
        const __half2* h2 = (const __half2*)&m2;
        const __half2* h3 = (const __half2*)&m3;
#pragma unroll
        for (int q = 0; q < 4; q++) {
            __half2 tq = __hadd2(__hadd2(h0[q], h1[q]), __hadd2(h2[q], h3[q]));
            float2 f = __half22float2(tq);
            acc[2 * q] += f.x;
            acc[2 * q + 1] += f.y;
        }
    }
    for (; e < end; e++) {
        int u = g_col[e];
        uint4 m = base[((size_t)u * D + c) >> 3];
        const __half2* h = (const __half2*)&m;
#pragma unroll
        for (int q = 0; q < 4; q++) {
            float2 f = __half22float2(h[q]);
            acc[2 * q] += f.x;
            acc[2 * q + 1] += f.y;
        }
    }
    float s = g_dinv[v];
    float4 b0 = *(const float4*)(bias + c);
    float4 b1 = *(const float4*)(bias + c + 4);
    float bb[8] = {b0.x, b0.y, b0.z, b0.w, b1.x, b1.y, b1.z, b1.w};
    uint4 pk;
    __half2* hv = (__half2*)&pk;
#pragma unroll
    for (int q = 0; q < 4; q++) {
        float r0 = s * acc[2 * q] + bb[2 * q];
        float r1 = s * acc[2 * q + 1] + bb[2 * q + 1];
        if (RELU) { r0 = fmaxf(r0, 0.f); r1 = fmaxf(r1, 0.f); }
        hv[q] = __floats2half2_rn(r0, r1);
    }
    ((uint4*)out)[selfidx] = pk;
}

// ---------------- host launch ----------------
extern "C" void kernel_launch(void* const* d_in, const int* in_sizes, int n_in,
                              void* d_out, int out_size) {
    const float* x   = (const float*)d_in[0];
    const float* y   = (const float*)d_in[1];
    const int*   ei  = (const int*)d_in[2];
    const float* Wg1 = (const float*)d_in[3];
    const float* bg1 = (const float*)d_in[4];
    const float* Wg2 = (const float*)d_in[5];
    const float* bg2 = (const float*)d_in[6];
    const float* Wl  = (const float*)d_in[7];
    const float* bl  = (const float*)d_in[8];
    const float* Wf  = (const float*)d_in[9];
    const float* bf  = (const float*)d_in[10];
    float* out = (float*)d_out;

    int n = in_sizes[0] / 128;
    int e = in_sizes[2] / 2;
    const int* src = ei;
    const int* dst = ei + e;

    __half *hA, *hB, *hH2, *hD;
    cudaGetSymbolAddress((void**)&hA, g_hA);
    cudaGetSymbolAddress((void**)&hB, g_hB);
    cudaGetSymbolAddress((void**)&hH2, g_hH2);
    cudaGetSymbolAddress((void**)&hD, g_hD);

    auto smem_sz = [](int K) -> size_t {
        size_t WsB = (size_t)K * (GBN + 8) * 2;
        size_t AsB = (size_t)GBM * (K + 8) * 2;
        size_t StB = (size_t)GBM * (GBN + 4) * 4;
        return WsB + (AsB > StB ? AsB : StB);
    };
    size_t sm64 = smem_sz(64), sm128 = smem_sz(128), sm192 = smem_sz(192);

    cudaFuncSetAttribute((const void*)gemm_wmma_kernel<128, 128, 128, 0, float>,
                         cudaFuncAttributeMaxDynamicSharedMemorySize, (int)sm128);
    cudaFuncSetAttribute((const void*)gemm_wmma_kernel<128, 128, 128, 0, __half>,
                         cudaFuncAttributeMaxDynamicSharedMemorySize, (int)sm128);
    cudaFuncSetAttribute((const void*)gemm_wmma_kernel<64, 64, 64, 0, float>,
                         cudaFuncAttributeMaxDynamicSharedMemorySize, (int)sm64);
    cudaFuncSetAttribute((const void*)gemm_wmma_kernel<64, 64, 64, 0, __half>,
                         cudaFuncAttributeMaxDynamicSharedMemorySize, (int)sm64);
    cudaFuncSetAttribute((const void*)gemm_wmma_kernel<192, 64, 128, 1, __half>,
                         cudaFuncAttributeMaxDynamicSharedMemorySize, (int)sm192);

    int nb_n = (n + 255) / 256;
    int nb_e = (e + 255) / 256;
    int nb_scan = (n + 1023) / 1024;

    // CSR + dinv
    zero_counts_kernel<<<nb_n, 256>>>(n);
    count_edges_kernel<<<nb_e, 256>>>(dst, e);
    scan1_kernel<<<nb_scan, 1024>>>(n);
    scan2_kernel<<<1, 128>>>(nb_scan);
    scan3_kernel<<<(n + 1023) / 1024, 1024>>>(n, nb_scan);
    scatter_edges_kernel<<<nb_e, 256>>>(src, dst, e);

    int rb = (n + GBM - 1) / GBM;
    dim3 g128(rb, 2);
    dim3 g64(rb, 1);
    int agg128_blocks = (int)(((size_t)n * 16 + 255) / 256);
    int agg64_blocks  = (int)(((size_t)n * 8 + 255) / 256);

    // feature branch
    gemm_wmma_kernel<128, 128, 128, 0, float><<<g128, 128, sm128>>>(
        x, nullptr, Wg1, nullptr, hA, n);
    agg_kernel<128, true><<<agg128_blocks, 256>>>(hA, bg1, hB, n);
    gemm_wmma_kernel<128, 128, 128, 0, __half><<<g128, 128, sm128>>>(
        hB, nullptr, Wg2, nullptr, hA, n);
    agg_kernel<128, false><<<agg128_blocks, 256>>>(hA, bg2, hH2, n);

    // label branch
    gemm_wmma_kernel<64, 64, 64, 0, float><<<g64, 128, sm64>>>(
        y, nullptr, Wl, nullptr, hA, n);
    agg_kernel<64, true><<<agg64_blocks, 256>>>(hA, bl, hD, n);
    for (int j = 1; j < 10; j++) {
        gemm_wmma_kernel<64, 64, 64, 0, __half><<<g64, 128, sm64>>>(
            hD, nullptr, Wl + (size_t)j * 64 * 64, nullptr, hA, n);
        if (j < 9)
            agg_kernel<64, true><<<agg64_blocks, 256>>>(
                hA, bl + (size_t)j * 64, hD, n);
        else
            agg_kernel<64, false><<<agg64_blocks, 256>>>(
                hA, bl + (size_t)j * 64, hD, n);
    }

    // final fused layer: sigmoid(concat(h2, xl) @ Wf + bf)
    gemm_wmma_kernel<192, 64, 128, 1, __half><<<g64, 128, sm192>>>(
        hH2, hD, Wf, bf, out, n);
}

// round 12
// speedup vs baseline: 1.0865x; 1.0865x over previous
#include <cuda_runtime.h>
#include <cuda_fp16.h>
#include <mma.h>
#include <math.h>

using namespace nvcuda;

#define NMAX 100000
#define EMAX 1600000

// ---------------- device scratch ----------------
__device__ float  g_dinv[NMAX];
__device__ int    g_cnt[NMAX];
__device__ int    g_fill[NMAX];
__device__ int    g_rowptr[NMAX + 1];
__device__ int    g_bsum[256];
__device__ int    g_col[EMAX];
__device__ __half g_hA[(size_t)NMAX * 128];
__device__ __half g_hB[(size_t)NMAX * 128];
__device__ __half g_hH2[(size_t)NMAX * 128];
__device__ __half g_hD[(size_t)NMAX * 64];

// ---------------- CSR build ----------------
__global__ void zero_counts_kernel(int n) {
    int i = blockIdx.x * blockDim.x + threadIdx.x;
    if (i < n) { g_cnt[i] = 0; g_fill[i] = 0; }
}

__global__ void count_edges_kernel(const int* __restrict__ dst, int e) {
    int i = blockIdx.x * blockDim.x + threadIdx.x;
    if (i < e) atomicAdd(&g_cnt[dst[i]], 1);
}

__global__ void scan1_kernel(int n) {
    __shared__ int s[1024];
    int tid = threadIdx.x;
    int i = blockIdx.x * 1024 + tid;
    int v = (i < n) ? g_cnt[i] : 0;
    s[tid] = v;
    __syncthreads();
    for (int off = 1; off < 1024; off <<= 1) {
        int t2 = (tid >= off) ? s[tid - off] : 0;
        __syncthreads();
        s[tid] += t2;
        __syncthreads();
    }
    if (i < n) {
        g_rowptr[i] = s[tid] - v;
        g_dinv[i] = rsqrtf((float)(v + 1));
    }
    if (tid == 1023) g_bsum[blockIdx.x] = s[1023];
}

__global__ void scan2_kernel(int nb) {
    __shared__ int s[128];
    int tid = threadIdx.x;
    int v = (tid < nb) ? g_bsum[tid] : 0;
    s[tid] = v;
    __syncthreads();
    for (int off = 1; off < 128; off <<= 1) {
        int t2 = (tid >= off) ? s[tid - off] : 0;
        __syncthreads();
        s[tid] += t2;
        __syncthreads();
    }
    if (tid < nb) g_bsum[tid] = s[tid] - v;
    if (tid == 127) g_bsum[nb] = s[127];
}

__global__ void scan3_kernel(int n, int nb) {
    int i = blockIdx.x * blockDim.x + threadIdx.x;
    if (i < n) g_rowptr[i] += g_bsum[i >> 10];
    if (i == 0) g_rowptr[n] = g_bsum[nb];
}

__global__ void scatter_edges_kernel(const int* __restrict__ src,
                                     const int* __restrict__ dst, int e) {
    int i = blockIdx.x * blockDim.x + threadIdx.x;
    if (i < e) {
        int d = dst[i];
        int p = g_rowptr[d] + atomicAdd(&g_fill[d], 1);
        g_col[p] = src[i];
    }
}

// ---------------- wmma GEMM (vectorized loads) ----------------
#define GBM 128
#define GBN 64

template <int K, int C, int K1, int EPI, typename TA>
__global__ __launch_bounds__(128) void gemm_wmma_kernel(
    const TA* __restrict__ A1, const __half* __restrict__ A2,
    const float* __restrict__ W, const float* __restrict__ bias,
    void* __restrict__ outv, int n) {
    constexpr int LDW = GBN + 8;   // halves
    constexpr int LDA = K + 8;     // halves
    constexpr int LDS_ = GBN + 4;  // floats
    extern __shared__ char smraw[];
    __half* Ws = (__half*)smraw;
    __half* As = (__half*)(smraw + (size_t)K * LDW * 2);
    float*  St = (float*)(smraw + (size_t)K * LDW * 2);

    const int t = threadIdx.x;
    const int w = t >> 5;
    const int row0 = blockIdx.x * GBM;
    const int bn0 = blockIdx.y * GBN;

    // load W tile [K][BN]: float4 loads, packed half2 x2 store (8B)
    for (int idx = t; idx < K * GBN / 4; idx += 128) {
        int k = idx / (GBN / 4);
        int j = (idx % (GBN / 4)) * 4;
        float4 wv = *(const float4*)(W + (size_t)k * C + bn0 + j);
        uint2 pk;
        __half2* h = (__half2*)&pk;
        h[0] = __floats2half2_rn(wv.x, wv.y);
        h[1] = __floats2half2_rn(wv.z, wv.w);
        *(uint2*)&Ws[k * LDW + j] = pk;
    }

    // load A tile [BM][K], pre-scaled by dinv when EPI==0
    constexpr int CPR = K / 8;  // 8-half chunks per row
#pragma unroll
    for (int it = 0; it < GBM * CPR / 128; it++) {
        int cidx = t + it * 128;
        int r = cidx / CPR;
        int kq = (cidx % CPR) * 8;
        int gr = row0 + r;
        uint4 pk = make_uint4(0, 0, 0, 0);
        if (gr < n) {
            float s = (EPI == 0) ? g_dinv[gr] : 1.0f;
            __half2 s2 = __float2half2_rn(s);
            if (kq < K1) {
                if (sizeof(TA) == 2) {  // half source: uint4 load + half2 scale
                    uint4 raw = *(const uint4*)((const __half*)A1 +
                                                (size_t)gr * K1 + kq);
                    __half2* h = (__half2*)&raw;
                    if (EPI == 0) {
#pragma unroll
                        for (int q = 0; q < 4; q++) h[q] = __hmul2(h[q], s2);
                    }
                    pk = raw;
                } else {  // float source: two float4 loads
                    const float* p = (const float*)A1 + (size_t)gr * K1 + kq;
                    float4 a = *(const float4*)p;
                    float4 b = *(const float4*)(p + 4);
                    __half2* h = (__half2*)&pk;
                    h[0] = __floats2half2_rn(s * a.x, s * a.y);
                    h[1] = __floats2half2_rn(s * a.z, s * a.w);
                    h[2] = __floats2half2_rn(s * b.x, s * b.y);
                    h[3] = __floats2half2_rn(s * b.z, s * b.w);
                }
            } else {
                uint4 raw = *(const uint4*)(A2 + (size_t)gr * (K - K1) +
                                            (kq - K1));
                __half2* h = (__half2*)&raw;
                if (EPI == 0) {
#pragma unroll
                    for (int q = 0; q < 4; q++) h[q] = __hmul2(h[q], s2);
                }
                pk = raw;
            }
        }
        *(uint4*)&As[r * LDA + kq] = pk;
    }
    __syncthreads();

    wmma::fragment<wmma::accumulator, 16, 16, 16, float> acc[2][4];
#pragma unroll
    for (int i = 0; i < 2; i++)
#pragma unroll
        for (int j = 0; j < 4; j++) wmma::fill_fragment(acc[i][j], 0.f);

    for (int k = 0; k < K; k += 16) {
        wmma::fragment<wmma::matrix_a, 16, 16, 16, __half, wmma::row_major> af[2];
        wmma::fragment<wmma::matrix_b, 16, 16, 16, __half, wmma::row_major> bfr[4];
        wmma::load_matrix_sync(af[0], As + (w * 32 + 0) * LDA + k, LDA);
        wmma::load_matrix_sync(af[1], As + (w * 32 + 16) * LDA + k, LDA);
#pragma unroll
        for (int j = 0; j < 4; j++)
            wmma::load_matrix_sync(bfr[j], Ws + k * LDW + j * 16, LDW);
#pragma unroll
        for (int i = 0; i < 2; i++)
#pragma unroll
            for (int j = 0; j < 4; j++)
                wmma::mma_sync(acc[i][j], af[i], bfr[j], acc[i][j]);
    }

    __syncthreads();
#pragma unroll
    for (int i = 0; i < 2; i++)
#pragma unroll
        for (int j = 0; j < 4; j++)
            wmma::store_matrix_sync(St + (w * 32 + i * 16) * LDS_ + j * 16,
                                    acc[i][j], LDS_, wmma::mem_row_major);
    __syncthreads();

    const int lane = t & 7;
    const int rsub = t >> 3;
#pragma unroll
    for (int g = 0; g < 8; g++) {
        int r = g * 16 + rsub;
        int gr = row0 + r;
        if (gr >= n) continue;
        const float* sp = St + r * LDS_ + lane * 8;
        if (EPI == 0) {
            uint4 pk;
            __half2* h = (__half2*)&pk;
            h[0] = __floats2half2_rn(sp[0], sp[1]);
            h[1] = __floats2half2_rn(sp[2], sp[3]);
            h[2] = __floats2half2_rn(sp[4], sp[5]);
            h[3] = __floats2half2_rn(sp[6], sp[7]);
            *(uint4*)((__half*)outv + (size_t)gr * C + bn0 + lane * 8) = pk;
        } else {
            float* outp = (float*)outv + (size_t)gr * C + bn0 + lane * 8;
            const float* bp = bias + bn0 + lane * 8;
            float ov[8];
#pragma unroll
            for (int q = 0; q < 8; q++)
                ov[q] = 1.f / (1.f + __expf(-(sp[q] + bp[q])));
            *(float4*)outp = *(float4*)ov;
            *(float4*)(outp + 4) = *(float4*)(ov + 4);
        }
    }
}

// ---------------- aggregation: 8-wide unroll, half2 trees, fp32 sum ----------
template <int D, bool RELU>
__global__ __launch_bounds__(256) void agg_kernel(
    const __half* __restrict__ hs, const float* __restrict__ bias,
    __half* __restrict__ out, int n) {
    constexpr int LPN = D / 8;  // lanes per node, 8 halfs each
    int idx = blockIdx.x * blockDim.x + threadIdx.x;
    int v = idx / LPN;
    int lane = idx % LPN;
    if (v >= n) return;
    int c = lane * 8;
    const uint4* base = (const uint4*)hs;
    size_t selfidx = ((size_t)v * D + c) >> 3;

    float acc[8];
    {
        uint4 sv = base[selfidx];
        const __half2* h = (const __half2*)&sv;
#pragma unroll
        for (int q = 0; q < 4; q++) {
            float2 f = __half22float2(h[q]);
            acc[2 * q] = f.x; acc[2 * q + 1] = f.y;
        }
    }
    int e = g_rowptr[v];
    const int end = g_rowptr[v + 1];

    // main loop: 8 edges in flight per thread
    for (; e + 7 < end; e += 8) {
        int u0 = g_col[e],     u1 = g_col[e + 1];
        int u2 = g_col[e + 2], u3 = g_col[e + 3];
        int u4 = g_col[e + 4], u5 = g_col[e + 5];
        int u6 = g_col[e + 6], u7 = g_col[e + 7];
        uint4 m0 = base[((size_t)u0 * D + c) >> 3];
        uint4 m1 = base[((size_t)u1 * D + c) >> 3];
        uint4 m2 = base[((size_t)u2 * D + c) >> 3];
        uint4 m3 = base[((size_t)u3 * D + c) >> 3];
        uint4 m4 = base[((size_t)u4 * D + c) >> 3];
        uint4 m5 = base[((size_t)u5 * D + c) >> 3];
        uint4 m6 = base[((size_t)u6 * D + c) >> 3];
        uint4 m7 = base[((size_t)u7 * D + c) >> 3];
        const __half2* h0 = (const __half2*)&m0;
        const __half2* h1 = (const __half2*)&m1;
        const __half2* h2 = (const __half2*)&m2;
        const __half2* h3 = (const __half2*)&m3;
        const __half2* h4 = (const __half2*)&m4;
        const __half2* h5 = (const __half2*)&m5;
        const __half2* h6 = (const __half2*)&m6;
        const __half2* h7 = (const __half2*)&m7;
#pragma unroll
        for (int q = 0; q < 4; q++) {
            // two independent 4-value half2 trees, joined in fp32
            __half2 ta = __hadd2(__hadd2(h0[q], h1[q]), __hadd2(h2[q], h3[q]));
            __half2 tb = __hadd2(__hadd2(h4[q], h5[q]), __hadd2(h6[q], h7[q]));
            float2 fa = __half22float2(ta);
            float2 fb = __half22float2(tb);
            acc[2 * q] += fa.x + fb.x;
            acc[2 * q + 1] += fa.y + fb.y;
        }
    }
    // 4-wide
    for (; e + 3 < end; e += 4) {
        int u0 = g_col[e],     u1 = g_col[e + 1];
        int u2 = g_col[e + 2], u3 = g_col[e + 3];
        uint4 m0 = base[((size_t)u0 * D + c) >> 3];
        uint4 m1 = base[((size_t)u1 * D + c) >> 3];
        uint4 m2 = base[((size_t)u2 * D + c) >> 3];
        uint4 m3 = base[((size_t)u3 * D + c) >> 3];
        const __half2* h0 = (const __half2*)&m0;
        const __half2* h1 = (const __half2*)&m1;
        const __half2* h2 = (const __half2*)&m2;
        const __half2* h3 = (const __half2*)&m3;
#pragma unroll
        for (int q = 0; q < 4; q++) {
            __half2 tq = __hadd2(__hadd2(h0[q], h1[q]), __hadd2(h2[q], h3[q]));
            float2 f = __half22float2(tq);
            acc[2 * q] += f.x;
            acc[2 * q + 1] += f.y;
        }
    }
    // scalar tail
    for (; e < end; e++) {
        int u = g_col[e];
        uint4 m = base[((size_t)u * D + c) >> 3];
        const __half2* h = (const __half2*)&m;
#pragma unroll
        for (int q = 0; q < 4; q++) {
            float2 f = __half22float2(h[q]);
            acc[2 * q] += f.x;
            acc[2 * q + 1] += f.y;
        }
    }
    float s = g_dinv[v];
    float4 b0 = *(const float4*)(bias + c);
    float4 b1 = *(const float4*)(bias + c + 4);
    float bb[8] = {b0.x, b0.y, b0.z, b0.w, b1.x, b1.y, b1.z, b1.w};
    uint4 pk;
    __half2* hv = (__half2*)&pk;
#pragma unroll
    for (int q = 0; q < 4; q++) {
        float r0 = s * acc[2 * q] + bb[2 * q];
        float r1 = s * acc[2 * q + 1] + bb[2 * q + 1];
        if (RELU) { r0 = fmaxf(r0, 0.f); r1 = fmaxf(r1, 0.f); }
        hv[q] = __floats2half2_rn(r0, r1);
    }
    ((uint4*)out)[selfidx] = pk;
}

// ---------------- host launch ----------------
extern "C" void kernel_launch(void* const* d_in, const int* in_sizes, int n_in,
                              void* d_out, int out_size) {
    const float* x   = (const float*)d_in[0];
    const float* y   = (const float*)d_in[1];
    const int*   ei  = (const int*)d_in[2];
    const float* Wg1 = (const float*)d_in[3];
    const float* bg1 = (const float*)d_in[4];
    const float* Wg2 = (const float*)d_in[5];
    const float* bg2 = (const float*)d_in[6];
    const float* Wl  = (const float*)d_in[7];
    const float* bl  = (const float*)d_in[8];
    const float* Wf  = (const float*)d_in[9];
    const float* bf  = (const float*)d_in[10];
    float* out = (float*)d_out;

    int n = in_sizes[0] / 128;
    int e = in_sizes[2] / 2;
    const int* src = ei;
    const int* dst = ei + e;

    __half *hA, *hB, *hH2, *hD;
    cudaGetSymbolAddress((void**)&hA, g_hA);
    cudaGetSymbolAddress((void**)&hB, g_hB);
    cudaGetSymbolAddress((void**)&hH2, g_hH2);
    cudaGetSymbolAddress((void**)&hD, g_hD);

    auto smem_sz = [](int K) -> size_t {
        size_t WsB = (size_t)K * (GBN + 8) * 2;
        size_t AsB = (size_t)GBM * (K + 8) * 2;
        size_t StB = (size_t)GBM * (GBN + 4) * 4;
        return WsB + (AsB > StB ? AsB : StB);
    };
    size_t sm64 = smem_sz(64), sm128 = smem_sz(128), sm192 = smem_sz(192);

    cudaFuncSetAttribute((const void*)gemm_wmma_kernel<128, 128, 128, 0, float>,
                         cudaFuncAttributeMaxDynamicSharedMemorySize, (int)sm128);
    cudaFuncSetAttribute((const void*)gemm_wmma_kernel<128, 128, 128, 0, __half>,
                         cudaFuncAttributeMaxDynamicSharedMemorySize, (int)sm128);
    cudaFuncSetAttribute((const void*)gemm_wmma_kernel<64, 64, 64, 0, float>,
                         cudaFuncAttributeMaxDynamicSharedMemorySize, (int)sm64);
    cudaFuncSetAttribute((const void*)gemm_wmma_kernel<64, 64, 64, 0, __half>,
                         cudaFuncAttributeMaxDynamicSharedMemorySize, (int)sm64);
    cudaFuncSetAttribute((const void*)gemm_wmma_kernel<192, 64, 128, 1, __half>,
                         cudaFuncAttributeMaxDynamicSharedMemorySize, (int)sm192);

    int nb_n = (n + 255) / 256;
    int nb_e = (e + 255) / 256;
    int nb_scan = (n + 1023) / 1024;

    // CSR + dinv
    zero_counts_kernel<<<nb_n, 256>>>(n);
    count_edges_kernel<<<nb_e, 256>>>(dst, e);
    scan1_kernel<<<nb_scan, 1024>>>(n);
    scan2_kernel<<<1, 128>>>(nb_scan);
    scan3_kernel<<<(n + 1023) / 1024, 1024>>>(n, nb_scan);
    scatter_edges_kernel<<<nb_e, 256>>>(src, dst, e);

    int rb = (n + GBM - 1) / GBM;
    dim3 g128(rb, 2);
    dim3 g64(rb, 1);
    int agg128_blocks = (int)(((size_t)n * 16 + 255) / 256);
    int agg64_blocks  = (int)(((size_t)n * 8 + 255) / 256);

    // feature branch
    gemm_wmma_kernel<128, 128, 128, 0, float><<<g128, 128, sm128>>>(
        x, nullptr, Wg1, nullptr, hA, n);
    agg_kernel<128, true><<<agg128_blocks, 256>>>(hA, bg1, hB, n);
    gemm_wmma_kernel<128, 128, 128, 0, __half><<<g128, 128, sm128>>>(
        hB, nullptr, Wg2, nullptr, hA, n);
    agg_kernel<128, false><<<agg128_blocks, 256>>>(hA, bg2, hH2, n);

    // label branch
    gemm_wmma_kernel<64, 64, 64, 0, float><<<g64, 128, sm64>>>(
        y, nullptr, Wl, nullptr, hA, n);
    agg_kernel<64, true><<<agg64_blocks, 256>>>(hA, bl, hD, n);
    for (int j = 1; j < 10; j++) {
        gemm_wmma_kernel<64, 64, 64, 0, __half><<<g64, 128, sm64>>>(
            hD, nullptr, Wl + (size_t)j * 64 * 64, nullptr, hA, n);
        if (j < 9)
            agg_kernel<64, true><<<agg64_blocks, 256>>>(
                hA, bl + (size_t)j * 64, hD, n);
        else
            agg_kernel<64, false><<<agg64_blocks, 256>>>(
                hA, bl + (size_t)j * 64, hD, n);
    }

    // final fused layer: sigmoid(concat(h2, xl) @ Wf + bf)
    gemm_wmma_kernel<192, 64, 128, 1, __half><<<g64, 128, sm192>>>(
        hH2, hD, Wf, bf, out, n);
}

// round 13
// speedup vs baseline: 1.1545x; 1.0626x over previous
#include <cuda_runtime.h>
#include <cuda_fp16.h>
#include <mma.h>
#include <math.h>

using namespace nvcuda;

#define NMAX 100000
#define EMAX 1600000

// ---------------- device scratch ----------------
__device__ float  g_dinv[NMAX];
__device__ int    g_cnt[NMAX];
__device__ int    g_fill[NMAX];
__device__ int    g_rowptr[NMAX + 1];
__device__ int    g_bsum[256];
__device__ int    g_col[EMAX];
__device__ __half g_hA[(size_t)NMAX * 128];
__device__ __half g_hB[(size_t)NMAX * 128];
__device__ __half g_hH2[(size_t)NMAX * 128];
__device__ __half g_hD[(size_t)NMAX * 64];
// preconverted fp16 weights:
//   [0]      Wg1 128x128
//   [16384]  Wg2 128x128
//   [32768]  Wl  10x64x64
//   [73728]  Wf  192x64
__device__ __half g_W[86016];

// ---------------- weight preconversion ----------------
__global__ void convert_w_kernel(const float* __restrict__ Wg1,
                                 const float* __restrict__ Wg2,
                                 const float* __restrict__ Wl,
                                 const float* __restrict__ Wf) {
    int i4 = blockIdx.x * blockDim.x + threadIdx.x;  // one float4 per thread
    int base = i4 * 4;
    if (base >= 86016) return;
    const float* src;
    int off;
    if (base < 16384)      { src = Wg1; off = base; }
    else if (base < 32768) { src = Wg2; off = base - 16384; }
    else if (base < 73728) { src = Wl;  off = base - 32768; }
    else                   { src = Wf;  off = base - 73728; }
    float4 v = *(const float4*)(src + off);
    uint2 pk;
    __half2* h = (__half2*)&pk;
    h[0] = __floats2half2_rn(v.x, v.y);
    h[1] = __floats2half2_rn(v.z, v.w);
    *(uint2*)&g_W[base] = pk;
}

// ---------------- CSR build ----------------
__global__ void zero_counts_kernel(int n) {
    int i = blockIdx.x * blockDim.x + threadIdx.x;
    if (i < n) { g_cnt[i] = 0; g_fill[i] = 0; }
}

__global__ void count_edges_kernel(const int* __restrict__ dst, int e) {
    int i = blockIdx.x * blockDim.x + threadIdx.x;
    if (i < e) atomicAdd(&g_cnt[dst[i]], 1);
}

__global__ void scan1_kernel(int n) {
    __shared__ int s[1024];
    int tid = threadIdx.x;
    int i = blockIdx.x * 1024 + tid;
    int v = (i < n) ? g_cnt[i] : 0;
    s[tid] = v;
    __syncthreads();
    for (int off = 1; off < 1024; off <<= 1) {
        int t2 = (tid >= off) ? s[tid - off] : 0;
        __syncthreads();
        s[tid] += t2;
        __syncthreads();
    }
    if (i < n) {
        g_rowptr[i] = s[tid] - v;
        g_dinv[i] = rsqrtf((float)(v + 1));
    }
    if (tid == 1023) g_bsum[blockIdx.x] = s[1023];
}

__global__ void scan2_kernel(int nb) {
    __shared__ int s[128];
    int tid = threadIdx.x;
    int v = (tid < nb) ? g_bsum[tid] : 0;
    s[tid] = v;
    __syncthreads();
    for (int off = 1; off < 128; off <<= 1) {
        int t2 = (tid >= off) ? s[tid - off] : 0;
        __syncthreads();
        s[tid] += t2;
        __syncthreads();
    }
    if (tid < nb) g_bsum[tid] = s[tid] - v;
    if (tid == 127) g_bsum[nb] = s[127];
}

__global__ void scan3_kernel(int n, int nb) {
    int i = blockIdx.x * blockDim.x + threadIdx.x;
    if (i < n) g_rowptr[i] += g_bsum[i >> 10];
    if (i == 0) g_rowptr[n] = g_bsum[nb];
}

__global__ void scatter_edges_kernel(const int* __restrict__ src,
                                     const int* __restrict__ dst, int e) {
    int i = blockIdx.x * blockDim.x + threadIdx.x;
    if (i < e) {
        int d = dst[i];
        int p = g_rowptr[d] + atomicAdd(&g_fill[d], 1);
        g_col[p] = src[i];
    }
}

// ---------------- wmma GEMM (half W, vectorized loads) ----------------
#define GBM 128
#define GBN 64

template <int K, int C, int K1, int EPI, typename TA>
__global__ __launch_bounds__(128) void gemm_wmma_kernel(
    const TA* __restrict__ A1, const __half* __restrict__ A2,
    const __half* __restrict__ Wh, const float* __restrict__ bias,
    void* __restrict__ outv, int n) {
    constexpr int LDW = GBN + 8;   // halves
    constexpr int LDA = K + 8;     // halves
    constexpr int LDS_ = GBN + 4;  // floats
    extern __shared__ char smraw[];
    __half* Ws = (__half*)smraw;
    __half* As = (__half*)(smraw + (size_t)K * LDW * 2);
    float*  St = (float*)(smraw + (size_t)K * LDW * 2);

    const int t = threadIdx.x;
    const int w = t >> 5;
    const int row0 = blockIdx.x * GBM;
    const int bn0 = blockIdx.y * GBN;

    // load W tile [K][BN]: uint4 half loads (8 halves each)
    for (int idx = t; idx < K * GBN / 8; idx += 128) {
        int k = idx / (GBN / 8);
        int j = (idx % (GBN / 8)) * 8;
        *(uint4*)&Ws[k * LDW + j] =
            *(const uint4*)(Wh + (size_t)k * C + bn0 + j);
    }

    // load A tile [BM][K], pre-scaled by dinv when EPI==0
    constexpr int CPR = K / 8;  // 8-half chunks per row
#pragma unroll
    for (int it = 0; it < GBM * CPR / 128; it++) {
        int cidx = t + it * 128;
        int r = cidx / CPR;
        int kq = (cidx % CPR) * 8;
        int gr = row0 + r;
        uint4 pk = make_uint4(0, 0, 0, 0);
        if (gr < n) {
            float s = (EPI == 0) ? g_dinv[gr] : 1.0f;
            __half2 s2 = __float2half2_rn(s);
            if (kq < K1) {
                if (sizeof(TA) == 2) {  // half source: uint4 load + half2 scale
                    uint4 raw = *(const uint4*)((const __half*)A1 +
                                                (size_t)gr * K1 + kq);
                    __half2* h = (__half2*)&raw;
                    if (EPI == 0) {
#pragma unroll
                        for (int q = 0; q < 4; q++) h[q] = __hmul2(h[q], s2);
                    }
                    pk = raw;
                } else {  // float source: two float4 loads
                    const float* p = (const float*)A1 + (size_t)gr * K1 + kq;
                    float4 a = *(const float4*)p;
                    float4 b = *(const float4*)(p + 4);
                    __half2* h = (__half2*)&pk;
                    h[0] = __floats2half2_rn(s * a.x, s * a.y);
                    h[1] = __floats2half2_rn(s * a.z, s * a.w);
                    h[2] = __floats2half2_rn(s * b.x, s * b.y);
                    h[3] = __floats2half2_rn(s * b.z, s * b.w);
                }
            } else {
                uint4 raw = *(const uint4*)(A2 + (size_t)gr * (K - K1) +
                                            (kq - K1));
                __half2* h = (__half2*)&raw;
                if (EPI == 0) {
#pragma unroll
                    for (int q = 0; q < 4; q++) h[q] = __hmul2(h[q], s2);
                }
                pk = raw;
            }
        }
        *(uint4*)&As[r * LDA + kq] = pk;
    }
    __syncthreads();

    wmma::fragment<wmma::accumulator, 16, 16, 16, float> acc[2][4];
#pragma unroll
    for (int i = 0; i < 2; i++)
#pragma unroll
        for (int j = 0; j < 4; j++) wmma::fill_fragment(acc[i][j], 0.f);

    for (int k = 0; k < K; k += 16) {
        wmma::fragment<wmma::matrix_a, 16, 16, 16, __half, wmma::row_major> af[2];
        wmma::fragment<wmma::matrix_b, 16, 16, 16, __half, wmma::row_major> bfr[4];
        wmma::load_matrix_sync(af[0], As + (w * 32 + 0) * LDA + k, LDA);
        wmma::load_matrix_sync(af[1], As + (w * 32 + 16) * LDA + k, LDA);
#pragma unroll
        for (int j = 0; j < 4; j++)
            wmma::load_matrix_sync(bfr[j], Ws + k * LDW + j * 16, LDW);
#pragma unroll
        for (int i = 0; i < 2; i++)
#pragma unroll
            for (int j = 0; j < 4; j++)
                wmma::mma_sync(acc[i][j], af[i], bfr[j], acc[i][j]);
    }

    __syncthreads();
#pragma unroll
    for (int i = 0; i < 2; i++)
#pragma unroll
        for (int j = 0; j < 4; j++)
            wmma::store_matrix_sync(St + (w * 32 + i * 16) * LDS_ + j * 16,
                                    acc[i][j], LDS_, wmma::mem_row_major);
    __syncthreads();

    const int lane = t & 7;
    const int rsub = t >> 3;
#pragma unroll
    for (int g = 0; g < 8; g++) {
        int r = g * 16 + rsub;
        int gr = row0 + r;
        if (gr >= n) continue;
        const float* sp = St + r * LDS_ + lane * 8;
        if (EPI == 0) {
            uint4 pk;
            __half2* h = (__half2*)&pk;
            h[0] = __floats2half2_rn(sp[0], sp[1]);
            h[1] = __floats2half2_rn(sp[2], sp[3]);
            h[2] = __floats2half2_rn(sp[4], sp[5]);
            h[3] = __floats2half2_rn(sp[6], sp[7]);
            *(uint4*)((__half*)outv + (size_t)gr * C + bn0 + lane * 8) = pk;
        } else {
            float* outp = (float*)outv + (size_t)gr * C + bn0 + lane * 8;
            const float* bp = bias + bn0 + lane * 8;
            float ov[8];
#pragma unroll
            for (int q = 0; q < 8; q++)
                ov[q] = 1.f / (1.f + __expf(-(sp[q] + bp[q])));
            *(float4*)outp = *(float4*)ov;
            *(float4*)(outp + 4) = *(float4*)(ov + 4);
        }
    }
}

// ---------------- aggregation: 8-wide unroll, half2 trees, fp32 sum ----------
template <int D, bool RELU>
__global__ __launch_bounds__(256) void agg_kernel(
    const __half* __restrict__ hs, const float* __restrict__ bias,
    __half* __restrict__ out, int n) {
    constexpr int LPN = D / 8;  // lanes per node, 8 halfs each
    int idx = blockIdx.x * blockDim.x + threadIdx.x;
    int v = idx / LPN;
    int lane = idx % LPN;
    if (v >= n) return;
    int c = lane * 8;
    const uint4* base = (const uint4*)hs;
    size_t selfidx = ((size_t)v * D + c) >> 3;

    float acc[8];
    {
        uint4 sv = base[selfidx];
        const __half2* h = (const __half2*)&sv;
#pragma unroll
        for (int q = 0; q < 4; q++) {
            float2 f = __half22float2(h[q]);
            acc[2 * q] = f.x; acc[2 * q + 1] = f.y;
        }
    }
    int e = g_rowptr[v];
    const int end = g_rowptr[v + 1];

    for (; e + 7 < end; e += 8) {
        int u0 = g_col[e],     u1 = g_col[e + 1];
        int u2 = g_col[e + 2], u3 = g_col[e + 3];
        int u4 = g_col[e + 4], u5 = g_col[e + 5];
        int u6 = g_col[e + 6], u7 = g_col[e + 7];
        uint4 m0 = base[((size_t)u0 * D + c) >> 3];
        uint4 m1 = base[((size_t)u1 * D + c) >> 3];
        uint4 m2 = base[((size_t)u2 * D + c) >> 3];
        uint4 m3 = base[((size_t)u3 * D + c) >> 3];
        uint4 m4 = base[((size_t)u4 * D + c) >> 3];
        uint4 m5 = base[((size_t)u5 * D + c) >> 3];
        uint4 m6 = base[((size_t)u6 * D + c) >> 3];
        uint4 m7 = base[((size_t)u7 * D + c) >> 3];
        const __half2* h0 = (const __half2*)&m0;
        const __half2* h1 = (const __half2*)&m1;
        const __half2* h2 = (const __half2*)&m2;
        const __half2* h3 = (const __half2*)&m3;
        const __half2* h4 = (const __half2*)&m4;
        const __half2* h5 = (const __half2*)&m5;
        const __half2* h6 = (const __half2*)&m6;
        const __half2* h7 = (const __half2*)&m7;
#pragma unroll
        for (int q = 0; q < 4; q++) {
            __half2 ta = __hadd2(__hadd2(h0[q], h1[q]), __hadd2(h2[q], h3[q]));
            __half2 tb = __hadd2(__hadd2(h4[q], h5[q]), __hadd2(h6[q], h7[q]));
            float2 fa = __half22float2(ta);
            float2 fb = __half22float2(tb);
            acc[2 * q] += fa.x + fb.x;
            acc[2 * q + 1] += fa.y + fb.y;
        }
    }
    for (; e + 3 < end; e += 4) {
        int u0 = g_col[e],     u1 = g_col[e + 1];
        int u2 = g_col[e + 2], u3 = g_col[e + 3];
        uint4 m0 = base[((size_t)u0 * D + c) >> 3];
        uint4 m1 = base[((size_t)u1 * D + c) >> 3];
        uint4 m2 = base[((size_t)u2 * D + c) >> 3];
        uint4 m3 = base[((size_t)u3 * D + c) >> 3];
        const __half2* h0 = (const __half2*)&m0;
        const __half2* h1 = (const __half2*)&m1;
        const __half2* h2 = (const __half2*)&m2;
        const __half2* h3 = (const __half2*)&m3;
#pragma unroll
        for (int q = 0; q < 4; q++) {
            __half2 tq = __hadd2(__hadd2(h0[q], h1[q]), __hadd2(h2[q], h3[q]));
            float2 f = __half22float2(tq);
            acc[2 * q] += f.x;
            acc[2 * q + 1] += f.y;
        }
    }
    for (; e < end; e++) {
        int u = g_col[e];
        uint4 m = base[((size_t)u * D + c) >> 3];
        const __half2* h = (const __half2*)&m;
#pragma unroll
        for (int q = 0; q < 4; q++) {
            float2 f = __half22float2(h[q]);
            acc[2 * q] += f.x;
            acc[2 * q + 1] += f.y;
        }
    }
    float s = g_dinv[v];
    float4 b0 = *(const float4*)(bias + c);
    float4 b1 = *(const float4*)(bias + c + 4);
    float bb[8] = {b0.x, b0.y, b0.z, b0.w, b1.x, b1.y, b1.z, b1.w};
    uint4 pk;
    __half2* hv = (__half2*)&pk;
#pragma unroll
    for (int q = 0; q < 4; q++) {
        float r0 = s * acc[2 * q] + bb[2 * q];
        float r1 = s * acc[2 * q + 1] + bb[2 * q + 1];
        if (RELU) { r0 = fmaxf(r0, 0.f); r1 = fmaxf(r1, 0.f); }
        hv[q] = __floats2half2_rn(r0, r1);
    }
    ((uint4*)out)[selfidx] = pk;
}

// ---------------- host launch ----------------
extern "C" void kernel_launch(void* const* d_in, const int* in_sizes, int n_in,
                              void* d_out, int out_size) {
    const float* x   = (const float*)d_in[0];
    const float* y   = (const float*)d_in[1];
    const int*   ei  = (const int*)d_in[2];
    const float* Wg1 = (const float*)d_in[3];
    const float* bg1 = (const float*)d_in[4];
    const float* Wg2 = (const float*)d_in[5];
    const float* bg2 = (const float*)d_in[6];
    const float* Wl  = (const float*)d_in[7];
    const float* bl  = (const float*)d_in[8];
    const float* Wf  = (const float*)d_in[9];
    const float* bf  = (const float*)d_in[10];
    float* out = (float*)d_out;

    int n = in_sizes[0] / 128;
    int e = in_sizes[2] / 2;
    const int* src = ei;
    const int* dst = ei + e;

    __half *hA, *hB, *hH2, *hD, *Wh;
    cudaGetSymbolAddress((void**)&hA, g_hA);
    cudaGetSymbolAddress((void**)&hB, g_hB);
    cudaGetSymbolAddress((void**)&hH2, g_hH2);
    cudaGetSymbolAddress((void**)&hD, g_hD);
    cudaGetSymbolAddress((void**)&Wh, g_W);
    const __half* Wg1h = Wh;
    const __half* Wg2h = Wh + 16384;
    const __half* Wlh  = Wh + 32768;
    const __half* Wfh  = Wh + 73728;

    auto smem_sz = [](int K) -> size_t {
        size_t WsB = (size_t)K * (GBN + 8) * 2;
        size_t AsB = (size_t)GBM * (K + 8) * 2;
        size_t StB = (size_t)GBM * (GBN + 4) * 4;
        return WsB + (AsB > StB ? AsB : StB);
    };
    size_t sm64 = smem_sz(64), sm128 = smem_sz(128), sm192 = smem_sz(192);

    cudaFuncSetAttribute((const void*)gemm_wmma_kernel<128, 128, 128, 0, float>,
                         cudaFuncAttributeMaxDynamicSharedMemorySize, (int)sm128);
    cudaFuncSetAttribute((const void*)gemm_wmma_kernel<128, 128, 128, 0, __half>,
                         cudaFuncAttributeMaxDynamicSharedMemorySize, (int)sm128);
    cudaFuncSetAttribute((const void*)gemm_wmma_kernel<64, 64, 64, 0, float>,
                         cudaFuncAttributeMaxDynamicSharedMemorySize, (int)sm64);
    cudaFuncSetAttribute((const void*)gemm_wmma_kernel<64, 64, 64, 0, __half>,
                         cudaFuncAttributeMaxDynamicSharedMemorySize, (int)sm64);
    cudaFuncSetAttribute((const void*)gemm_wmma_kernel<192, 64, 128, 1, __half>,
                         cudaFuncAttributeMaxDynamicSharedMemorySize, (int)sm192);

    int nb_n = (n + 255) / 256;
    int nb_e = (e + 255) / 256;
    int nb_scan = (n + 1023) / 1024;

    // weight preconversion (86016 halves = 21504 float4 threads)
    convert_w_kernel<<<(21504 + 255) / 256, 256>>>(Wg1, Wg2, Wl, Wf);

    // CSR + dinv
    zero_counts_kernel<<<nb_n, 256>>>(n);
    count_edges_kernel<<<nb_e, 256>>>(dst, e);
    scan1_kernel<<<nb_scan, 1024>>>(n);
    scan2_kernel<<<1, 128>>>(nb_scan);
    scan3_kernel<<<(n + 1023) / 1024, 1024>>>(n, nb_scan);
    scatter_edges_kernel<<<nb_e, 256>>>(src, dst, e);

    int rb = (n + GBM - 1) / GBM;
    dim3 g128(rb, 2);
    dim3 g64(rb, 1);
    int agg128_blocks = (int)(((size_t)n * 16 + 255) / 256);
    int agg64_blocks  = (int)(((size_t)n * 8 + 255) / 256);

    // feature branch
    gemm_wmma_kernel<128, 128, 128, 0, float><<<g128, 128, sm128>>>(
        x, nullptr, Wg1h, nullptr, hA, n);
    agg_kernel<128, true><<<agg128_blocks, 256>>>(hA, bg1, hB, n);
    gemm_wmma_kernel<128, 128, 128, 0, __half><<<g128, 128, sm128>>>(
        hB, nullptr, Wg2h, nullptr, hA, n);
    agg_kernel<128, false><<<agg128_blocks, 256>>>(hA, bg2, hH2, n);

    // label branch
    gemm_wmma_kernel<64, 64, 64, 0, float><<<g64, 128, sm64>>>(
        y, nullptr, Wlh, nullptr, hA, n);
    agg_kernel<64, true><<<agg64_blocks, 256>>>(hA, bl, hD, n);
    for (int j = 1; j < 10; j++) {
        gemm_wmma_kernel<64, 64, 64, 0, __half><<<g64, 128, sm64>>>(
            hD, nullptr, Wlh + (size_t)j * 64 * 64, nullptr, hA, n);
        if (j < 9)
            agg_kernel<64, true><<<agg64_blocks, 256>>>(
                hA, bl + (size_t)j * 64, hD, n);
        else
            agg_kernel<64, false><<<agg64_blocks, 256>>>(
                hA, bl + (size_t)j * 64, hD, n);
    }

    // final fused layer: sigmoid(concat(h2, xl) @ Wf + bf)
    gemm_wmma_kernel<192, 64, 128, 1, __half><<<g64, 128, sm192>>>(
        hH2, hD, Wfh, bf, out, n);
}

// round 14
// speedup vs baseline: 1.1874x; 1.0286x over previous
#include <cuda_runtime.h>
#include <cuda_fp16.h>
#include <mma.h>
#include <math.h>

using namespace nvcuda;

#define NMAX 100000
#define EMAX 1600000
#define NPAD (NMAX + 128)   // padded rows: GEMM tiles store full 128-row tiles

// ---------------- device scratch ----------------
__device__ float  g_dinv[NMAX];
__device__ int    g_cnt[NMAX];
__device__ int    g_fill[NMAX];
__device__ int    g_rowptr[NMAX + 1];
__device__ int    g_bsum[256];
__device__ int    g_col[EMAX];
__device__ __half g_hA[(size_t)NPAD * 128];
__device__ __half g_hB[(size_t)NPAD * 128];
__device__ __half g_hH2[(size_t)NPAD * 128];
__device__ __half g_hD[(size_t)NPAD * 64];
// preconverted fp16 weights: Wg1 | Wg2 | Wl(10) | Wf
__device__ __half g_W[86016];

// ---------------- init: zero counts + convert weights (merged) --------------
__global__ void init_kernel(const float* __restrict__ Wg1,
                            const float* __restrict__ Wg2,
                            const float* __restrict__ Wl,
                            const float* __restrict__ Wf, int n) {
    int i = blockIdx.x * blockDim.x + threadIdx.x;
    if (i < n) { g_cnt[i] = 0; g_fill[i] = 0; }
    if (i < 21504) {  // 86016 halves / 4 per thread
        int base = i * 4;
        const float* src;
        int off;
        if (base < 16384)      { src = Wg1; off = base; }
        else if (base < 32768) { src = Wg2; off = base - 16384; }
        else if (base < 73728) { src = Wl;  off = base - 32768; }
        else                   { src = Wf;  off = base - 73728; }
        float4 v = *(const float4*)(src + off);
        uint2 pk;
        __half2* h = (__half2*)&pk;
        h[0] = __floats2half2_rn(v.x, v.y);
        h[1] = __floats2half2_rn(v.z, v.w);
        *(uint2*)&g_W[base] = pk;
    }
}

// ---------------- CSR build ----------------
__global__ void count_edges_kernel(const int* __restrict__ dst, int e) {
    int i = blockIdx.x * blockDim.x + threadIdx.x;
    if (i < e) atomicAdd(&g_cnt[dst[i]], 1);
}

__global__ void scan1_kernel(int n) {
    __shared__ int s[1024];
    int tid = threadIdx.x;
    int i = blockIdx.x * 1024 + tid;
    int v = (i < n) ? g_cnt[i] : 0;
    s[tid] = v;
    __syncthreads();
    for (int off = 1; off < 1024; off <<= 1) {
        int t2 = (tid >= off) ? s[tid - off] : 0;
        __syncthreads();
        s[tid] += t2;
        __syncthreads();
    }
    if (i < n) {
        g_rowptr[i] = s[tid] - v;
        g_dinv[i] = rsqrtf((float)(v + 1));
    }
    if (tid == 1023) g_bsum[blockIdx.x] = s[1023];
}

__global__ void scan2_kernel(int nb) {
    __shared__ int s[128];
    int tid = threadIdx.x;
    int v = (tid < nb) ? g_bsum[tid] : 0;
    s[tid] = v;
    __syncthreads();
    for (int off = 1; off < 128; off <<= 1) {
        int t2 = (tid >= off) ? s[tid - off] : 0;
        __syncthreads();
        s[tid] += t2;
        __syncthreads();
    }
    if (tid < nb) g_bsum[tid] = s[tid] - v;
    if (tid == 127) g_bsum[nb] = s[127];
}

__global__ void scan3_kernel(int n, int nb) {
    int i = blockIdx.x * blockDim.x + threadIdx.x;
    if (i < n) g_rowptr[i] += g_bsum[i >> 10];
    if (i == 0) g_rowptr[n] = g_bsum[nb];
}

__global__ void scatter_edges_kernel(const int* __restrict__ src,
                                     const int* __restrict__ dst, int e) {
    int i = blockIdx.x * blockDim.x + threadIdx.x;
    if (i < e) {
        int d = dst[i];
        int p = g_rowptr[d] + atomicAdd(&g_fill[d], 1);
        g_col[p] = src[i];
    }
}

// ---------------- wmma GEMM ----------------
// EPI 0: half accumulators, direct global store (needs padded output rows)
// EPI 1: fp32 accum + smem staging + sigmoid, fp32 out (row-guarded)
#define GBM 128
#define GBN 64

template <int K, int C, int K1, int EPI, typename TA>
__global__ __launch_bounds__(128) void gemm_wmma_kernel(
    const TA* __restrict__ A1, const __half* __restrict__ A2,
    const __half* __restrict__ Wh, const float* __restrict__ bias,
    void* __restrict__ outv, int n) {
    constexpr int LDW = GBN + 8;   // halves
    constexpr int LDA = K + 8;     // halves
    constexpr int LDS_ = GBN + 4;  // floats (EPI=1 staging)
    extern __shared__ char smraw[];
    __half* Ws = (__half*)smraw;
    __half* As = (__half*)(smraw + (size_t)K * LDW * 2);
    float*  St = (float*)(smraw + (size_t)K * LDW * 2);

    const int t = threadIdx.x;
    const int w = t >> 5;
    const int row0 = blockIdx.x * GBM;
    const int bn0 = blockIdx.y * GBN;

    // load W tile [K][BN]: uint4 half loads
    for (int idx = t; idx < K * GBN / 8; idx += 128) {
        int k = idx / (GBN / 8);
        int j = (idx % (GBN / 8)) * 8;
        *(uint4*)&Ws[k * LDW + j] =
            *(const uint4*)(Wh + (size_t)k * C + bn0 + j);
    }

    // load A tile [BM][K], pre-scaled by dinv when EPI==0
    constexpr int CPR = K / 8;
#pragma unroll
    for (int it = 0; it < GBM * CPR / 128; it++) {
        int cidx = t + it * 128;
        int r = cidx / CPR;
        int kq = (cidx % CPR) * 8;
        int gr = row0 + r;
        uint4 pk = make_uint4(0, 0, 0, 0);
        if (gr < n) {
            float s = (EPI == 0) ? g_dinv[gr] : 1.0f;
            __half2 s2 = __float2half2_rn(s);
            if (kq < K1) {
                if (sizeof(TA) == 2) {
                    uint4 raw = *(const uint4*)((const __half*)A1 +
                                                (size_t)gr * K1 + kq);
                    __half2* h = (__half2*)&raw;
                    if (EPI == 0) {
#pragma unroll
                        for (int q = 0; q < 4; q++) h[q] = __hmul2(h[q], s2);
                    }
                    pk = raw;
                } else {
                    const float* p = (const float*)A1 + (size_t)gr * K1 + kq;
                    float4 a = *(const float4*)p;
                    float4 b = *(const float4*)(p + 4);
                    __half2* h = (__half2*)&pk;
                    h[0] = __floats2half2_rn(s * a.x, s * a.y);
                    h[1] = __floats2half2_rn(s * a.z, s * a.w);
                    h[2] = __floats2half2_rn(s * b.x, s * b.y);
                    h[3] = __floats2half2_rn(s * b.z, s * b.w);
                }
            } else {
                uint4 raw = *(const uint4*)(A2 + (size_t)gr * (K - K1) +
                                            (kq - K1));
                __half2* h = (__half2*)&raw;
                if (EPI == 0) {
#pragma unroll
                    for (int q = 0; q < 4; q++) h[q] = __hmul2(h[q], s2);
                }
                pk = raw;
            }
        }
        *(uint4*)&As[r * LDA + kq] = pk;
    }
    __syncthreads();

    if (EPI == 0) {
        // half accumulators, direct global store (rows padded)
        wmma::fragment<wmma::accumulator, 16, 16, 16, __half> acc[2][4];
#pragma unroll
        for (int i = 0; i < 2; i++)
#pragma unroll
            for (int j = 0; j < 4; j++)
                wmma::fill_fragment(acc[i][j], __float2half(0.f));
        for (int k = 0; k < K; k += 16) {
            wmma::fragment<wmma::matrix_a, 16, 16, 16, __half, wmma::row_major> af[2];
            wmma::fragment<wmma::matrix_b, 16, 16, 16, __half, wmma::row_major> bfr[4];
            wmma::load_matrix_sync(af[0], As + (w * 32 + 0) * LDA + k, LDA);
            wmma::load_matrix_sync(af[1], As + (w * 32 + 16) * LDA + k, LDA);
#pragma unroll
            for (int j = 0; j < 4; j++)
                wmma::load_matrix_sync(bfr[j], Ws + k * LDW + j * 16, LDW);
#pragma unroll
            for (int i = 0; i < 2; i++)
#pragma unroll
                for (int j = 0; j < 4; j++)
                    wmma::mma_sync(acc[i][j], af[i], bfr[j], acc[i][j]);
        }
        __half* outp = (__half*)outv;
#pragma unroll
        for (int i = 0; i < 2; i++)
#pragma unroll
            for (int j = 0; j < 4; j++)
                wmma::store_matrix_sync(
                    outp + (size_t)(row0 + w * 32 + i * 16) * C + bn0 + j * 16,
                    acc[i][j], C, wmma::mem_row_major);
    } else {
        wmma::fragment<wmma::accumulator, 16, 16, 16, float> acc[2][4];
#pragma unroll
        for (int i = 0; i < 2; i++)
#pragma unroll
            for (int j = 0; j < 4; j++) wmma::fill_fragment(acc[i][j], 0.f);
        for (int k = 0; k < K; k += 16) {
            wmma::fragment<wmma::matrix_a, 16, 16, 16, __half, wmma::row_major> af[2];
            wmma::fragment<wmma::matrix_b, 16, 16, 16, __half, wmma::row_major> bfr[4];
            wmma::load_matrix_sync(af[0], As + (w * 32 + 0) * LDA + k, LDA);
            wmma::load_matrix_sync(af[1], As + (w * 32 + 16) * LDA + k, LDA);
#pragma unroll
            for (int j = 0; j < 4; j++)
                wmma::load_matrix_sync(bfr[j], Ws + k * LDW + j * 16, LDW);
#pragma unroll
            for (int i = 0; i < 2; i++)
#pragma unroll
                for (int j = 0; j < 4; j++)
                    wmma::mma_sync(acc[i][j], af[i], bfr[j], acc[i][j]);
        }
        __syncthreads();
#pragma unroll
        for (int i = 0; i < 2; i++)
#pragma unroll
            for (int j = 0; j < 4; j++)
                wmma::store_matrix_sync(St + (w * 32 + i * 16) * LDS_ + j * 16,
                                        acc[i][j], LDS_, wmma::mem_row_major);
        __syncthreads();

        const int lane = t & 7;
        const int rsub = t >> 3;
#pragma unroll
        for (int g = 0; g < 8; g++) {
            int r = g * 16 + rsub;
            int gr = row0 + r;
            if (gr >= n) continue;
            const float* sp = St + r * LDS_ + lane * 8;
            float* outp = (float*)outv + (size_t)gr * C + bn0 + lane * 8;
            const float* bp = bias + bn0 + lane * 8;
            float ov[8];
#pragma unroll
            for (int q = 0; q < 8; q++)
                ov[q] = 1.f / (1.f + __expf(-(sp[q] + bp[q])));
            *(float4*)outp = *(float4*)ov;
            *(float4*)(outp + 4) = *(float4*)(ov + 4);
        }
    }
}

// ---------------- aggregation: 8-wide unroll, half2 trees, fp32 sum ----------
template <int D, bool RELU>
__global__ __launch_bounds__(256) void agg_kernel(
    const __half* __restrict__ hs, const float* __restrict__ bias,
    __half* __restrict__ out, int n) {
    constexpr int LPN = D / 8;
    int idx = blockIdx.x * blockDim.x + threadIdx.x;
    int v = idx / LPN;
    int lane = idx % LPN;
    if (v >= n) return;
    int c = lane * 8;
    const uint4* base = (const uint4*)hs;
    size_t selfidx = ((size_t)v * D + c) >> 3;

    float acc[8];
    {
        uint4 sv = base[selfidx];
        const __half2* h = (const __half2*)&sv;
#pragma unroll
        for (int q = 0; q < 4; q++) {
            float2 f = __half22float2(h[q]);
            acc[2 * q] = f.x; acc[2 * q + 1] = f.y;
        }
    }
    int e = g_rowptr[v];
    const int end = g_rowptr[v + 1];

    for (; e + 7 < end; e += 8) {
        int u0 = g_col[e],     u1 = g_col[e + 1];
        int u2 = g_col[e + 2], u3 = g_col[e + 3];
        int u4 = g_col[e + 4], u5 = g_col[e + 5];
        int u6 = g_col[e + 6], u7 = g_col[e + 7];
        uint4 m0 = base[((size_t)u0 * D + c) >> 3];
        uint4 m1 = base[((size_t)u1 * D + c) >> 3];
        uint4 m2 = base[((size_t)u2 * D + c) >> 3];
        uint4 m3 = base[((size_t)u3 * D + c) >> 3];
        uint4 m4 = base[((size_t)u4 * D + c) >> 3];
        uint4 m5 = base[((size_t)u5 * D + c) >> 3];
        uint4 m6 = base[((size_t)u6 * D + c) >> 3];
        uint4 m7 = base[((size_t)u7 * D + c) >> 3];
        const __half2* h0 = (const __half2*)&m0;
        const __half2* h1 = (const __half2*)&m1;
        const __half2* h2 = (const __half2*)&m2;
        const __half2* h3 = (const __half2*)&m3;
        const __half2* h4 = (const __half2*)&m4;
        const __half2* h5 = (const __half2*)&m5;
        const __half2* h6 = (const __half2*)&m6;
        const __half2* h7 = (const __half2*)&m7;
#pragma unroll
        for (int q = 0; q < 4; q++) {
            __half2 ta = __hadd2(__hadd2(h0[q], h1[q]), __hadd2(h2[q], h3[q]));
            __half2 tb = __hadd2(__hadd2(h4[q], h5[q]), __hadd2(h6[q], h7[q]));
            float2 fa = __half22float2(ta);
            float2 fb = __half22float2(tb);
            acc[2 * q] += fa.x + fb.x;
            acc[2 * q + 1] += fa.y + fb.y;
        }
    }
    for (; e + 3 < end; e += 4) {
        int u0 = g_col[e],     u1 = g_col[e + 1];
        int u2 = g_col[e + 2], u3 = g_col[e + 3];
        uint4 m0 = base[((size_t)u0 * D + c) >> 3];
        uint4 m1 = base[((size_t)u1 * D + c) >> 3];
        uint4 m2 = base[((size_t)u2 * D + c) >> 3];
        uint4 m3 = base[((size_t)u3 * D + c) >> 3];
        const __half2* h0 = (const __half2*)&m0;
        const __half2* h1 = (const __half2*)&m1;
        const __half2* h2 = (const __half2*)&m2;
        const __half2* h3 = (const __half2*)&m3;
#pragma unroll
        for (int q = 0; q < 4; q++) {
            __half2 tq = __hadd2(__hadd2(h0[q], h1[q]), __hadd2(h2[q], h3[q]));
            float2 f = __half22float2(tq);
            acc[2 * q] += f.x;
            acc[2 * q + 1] += f.y;
        }
    }
    for (; e < end; e++) {
        int u = g_col[e];
        uint4 m = base[((size_t)u * D + c) >> 3];
        const __half2* h = (const __half2*)&m;
#pragma unroll
        for (int q = 0; q < 4; q++) {
            float2 f = __half22float2(h[q]);
            acc[2 * q] += f.x;
            acc[2 * q + 1] += f.y;
        }
    }
    float s = g_dinv[v];
    float4 b0 = *(const float4*)(bias + c);
    float4 b1 = *(const float4*)(bias + c + 4);
    float bb[8] = {b0.x, b0.y, b0.z, b0.w, b1.x, b1.y, b1.z, b1.w};
    uint4 pk;
    __half2* hv = (__half2*)&pk;
#pragma unroll
    for (int q = 0; q < 4; q++) {
        float r0 = s * acc[2 * q] + bb[2 * q];
        float r1 = s * acc[2 * q + 1] + bb[2 * q + 1];
        if (RELU) { r0 = fmaxf(r0, 0.f); r1 = fmaxf(r1, 0.f); }
        hv[q] = __floats2half2_rn(r0, r1);
    }
    ((uint4*)out)[selfidx] = pk;
}

// ---------------- host launch ----------------
extern "C" void kernel_launch(void* const* d_in, const int* in_sizes, int n_in,
                              void* d_out, int out_size) {
    const float* x   = (const float*)d_in[0];
    const float* y   = (const float*)d_in[1];
    const int*   ei  = (const int*)d_in[2];
    const float* Wg1 = (const float*)d_in[3];
    const float* bg1 = (const float*)d_in[4];
    const float* Wg2 = (const float*)d_in[5];
    const float* bg2 = (const float*)d_in[6];
    const float* Wl  = (const float*)d_in[7];
    const float* bl  = (const float*)d_in[8];
    const float* Wf  = (const float*)d_in[9];
    const float* bf  = (const float*)d_in[10];
    float* out = (float*)d_out;

    int n = in_sizes[0] / 128;
    int e = in_sizes[2] / 2;
    const int* src = ei;
    const int* dst = ei + e;

    __half *hA, *hB, *hH2, *hD, *Wh;
    cudaGetSymbolAddress((void**)&hA, g_hA);
    cudaGetSymbolAddress((void**)&hB, g_hB);
    cudaGetSymbolAddress((void**)&hH2, g_hH2);
    cudaGetSymbolAddress((void**)&hD, g_hD);
    cudaGetSymbolAddress((void**)&Wh, g_W);
    const __half* Wg1h = Wh;
    const __half* Wg2h = Wh + 16384;
    const __half* Wlh  = Wh + 32768;
    const __half* Wfh  = Wh + 73728;

    // smem: EPI=0 needs Ws+As only; EPI=1 also needs St
    auto smem0 = [](int K) -> size_t {
        return (size_t)K * (GBN + 8) * 2 + (size_t)GBM * (K + 8) * 2;
    };
    auto smem1 = [](int K) -> size_t {
        size_t WsB = (size_t)K * (GBN + 8) * 2;
        size_t AsB = (size_t)GBM * (K + 8) * 2;
        size_t StB = (size_t)GBM * (GBN + 4) * 4;
        return WsB + (AsB > StB ? AsB : StB);
    };
    size_t sm64 = smem0(64), sm128 = smem0(128), sm192 = smem1(192);

    cudaFuncSetAttribute((const void*)gemm_wmma_kernel<128, 128, 128, 0, float>,
                         cudaFuncAttributeMaxDynamicSharedMemorySize, (int)sm128);
    cudaFuncSetAttribute((const void*)gemm_wmma_kernel<128, 128, 128, 0, __half>,
                         cudaFuncAttributeMaxDynamicSharedMemorySize, (int)sm128);
    cudaFuncSetAttribute((const void*)gemm_wmma_kernel<64, 64, 64, 0, float>,
                         cudaFuncAttributeMaxDynamicSharedMemorySize, (int)sm64);
    cudaFuncSetAttribute((const void*)gemm_wmma_kernel<64, 64, 64, 0, __half>,
                         cudaFuncAttributeMaxDynamicSharedMemorySize, (int)sm64);
    cudaFuncSetAttribute((const void*)gemm_wmma_kernel<192, 64, 128, 1, __half>,
                         cudaFuncAttributeMaxDynamicSharedMemorySize, (int)sm192);

    int nb_n = (n + 255) / 256;
    int nb_e = (e + 255) / 256;
    int nb_scan = (n + 1023) / 1024;

    // init (zero counts + convert weights), CSR + dinv
    init_kernel<<<nb_n, 256>>>(Wg1, Wg2, Wl, Wf, n);
    count_edges_kernel<<<nb_e, 256>>>(dst, e);
    scan1_kernel<<<nb_scan, 1024>>>(n);
    scan2_kernel<<<1, 128>>>(nb_scan);
    scan3_kernel<<<(n + 1023) / 1024, 1024>>>(n, nb_scan);
    scatter_edges_kernel<<<nb_e, 256>>>(src, dst, e);

    int rb = (n + GBM - 1) / GBM;
    dim3 g128(rb, 2);
    dim3 g64(rb, 1);
    int agg128_blocks = (int)(((size_t)n * 16 + 255) / 256);
    int agg64_blocks  = (int)(((size_t)n * 8 + 255) / 256);

    // feature branch
    gemm_wmma_kernel<128, 128, 128, 0, float><<<g128, 128, sm128>>>(
        x, nullptr, Wg1h, nullptr, hA, n);
    agg_kernel<128, true><<<agg128_blocks, 256>>>(hA, bg1, hB, n);
    gemm_wmma_kernel<128, 128, 128, 0, __half><<<g128, 128, sm128>>>(
        hB, nullptr, Wg2h, nullptr, hA, n);
    agg_kernel<128, false><<<agg128_blocks, 256>>>(hA, bg2, hH2, n);

    // label branch
    gemm_wmma_kernel<64, 64, 64, 0, float><<<g64, 128, sm64>>>(
        y, nullptr, Wlh, nullptr, hA, n);
    agg_kernel<64, true><<<agg64_blocks, 256>>>(hA, bl, hD, n);
    for (int j = 1; j < 10; j++) {
        gemm_wmma_kernel<64, 64, 64, 0, __half><<<g64, 128, sm64>>>(
            hD, nullptr, Wlh + (size_t)j * 64 * 64, nullptr, hA, n);
        if (j < 9)
            agg_kernel<64, true><<<agg64_blocks, 256>>>(
                hA, bl + (size_t)j * 64, hD, n);
        else
            agg_kernel<64, false><<<agg64_blocks, 256>>>(
                hA, bl + (size_t)j * 64, hD, n);
    }

    // final fused layer: sigmoid(concat(h2, xl) @ Wf + bf)
    gemm_wmma_kernel<192, 64, 128, 1, __half><<<g64, 128, sm192>>>(
        hH2, hD, Wfh, bf, out, n);
}